// round 5
// baseline (speedup 1.0000x reference)
#include <cuda_runtime.h>
#include <cstdint>
#include <cstddef>

#define NROWS 65536
#define DIMD  128
#define KC    1024
#define CT    128
#define NTILES (KC / CT)
#define SMEMSZ (128*32*4 + 128*128*4 + 32*4 + 128*4)

// Device-global scratch (allocation-free per harness rules)
__device__ unsigned long long g_S[KC * DIMD];  // fixed-point scatter sums (x * 2^40)
__device__ unsigned long long g_loss;          // fixed-point sum of sq diffs (* 2^30)
__device__ float g_csq[KC];
__device__ int   g_idx[NROWS];

// threefry2x32, key = jax.random.key(42) = [0, 42].
// JAX partitionable 32-bit draws (prng.py): counts = iota(uint64, n) -> counter
// (hi=0, lo=j); bits = out0 ^ out1 (XOR of both output words).
__device__ __forceinline__ uint32_t tf_xor(uint32_t c0, uint32_t c1) {
    const uint32_t ks0 = 0u, ks1 = 42u, ks2 = 0x1BD11BF0u; // 0x1BD11BDA ^ 0 ^ 42
    uint32_t x0 = c0 + ks0, x1 = c1 + ks1;
#define TFR(r) { x0 += x1; x1 = __funnelshift_l(x1, x1, (r)); x1 ^= x0; }
    TFR(13) TFR(15) TFR(26) TFR(6)   x0 += ks1; x1 += ks2 + 1u;
    TFR(17) TFR(29) TFR(16) TFR(24)  x0 += ks2; x1 += ks0 + 2u;
    TFR(13) TFR(15) TFR(26) TFR(6)   x0 += ks0; x1 += ks1 + 3u;
    TFR(17) TFR(29) TFR(16) TFR(24)  x0 += ks1; x1 += ks2 + 4u;
    TFR(13) TFR(15) TFR(26) TFR(6)   x0 += ks2; x1 += ks0 + 5u;
#undef TFR
    return x0 ^ x1;
}

// JAX gumbel: u = max(tiny, fl(bits_float - 1) + tiny); g = -log(-log(u))
__device__ __forceinline__ float gumbel_of(uint32_t bits) {
    const float tiny = 1.17549435e-38f;
    float f = __fsub_rn(__uint_as_float((bits >> 9) | 0x3F800000u), 1.0f);
    float u = fmaxf(tiny, __fadd_rn(f, tiny));
    return -logf(-logf(u));
}

// ---- prep: zero accumulators, fp64-exact codebook sq-norms rounded to f32 ----
__global__ void k_prep(const float* __restrict__ cb) {
    int k = blockIdx.x, t = threadIdx.x;
    g_S[k * DIMD + t] = 0ull;
    if (k == 0 && t == 0) g_loss = 0ull;
    float v = cb[k * DIMD + t];
    __shared__ double red[128];
    red[t] = (double)v * (double)v;
    __syncthreads();
    for (int o = 64; o > 0; o >>= 1) { if (t < o) red[t] += red[t + o]; __syncthreads(); }
    if (t == 0) g_csq[k] = (float)red[0];
}

// ---- main: distances + gumbel + argmax + one-hot write ----
__global__ void __launch_bounds__(256) k_main(const float* __restrict__ x,
                                              const float* __restrict__ cb,
                                              float* __restrict__ codes) {
    extern __shared__ float sm[];
    float* xs  = sm;                  // [128][32]  x tile transposed [d][localrow]
    float* cs  = sm + 128 * 32;       // [128][128] codebook tile transposed [d][code]
    float* asq = cs + 128 * 128;      // [32]
    float* bsq = asq + 32;            // [128]

    const int tid = threadIdx.x;
    const int w = tid >> 5, l = tid & 31;
    const int r0 = blockIdx.x * 32;

    // Load x tile transposed
    {
        int j = tid >> 3, q = tid & 7;
        const float4* src = (const float4*)(x + (size_t)(r0 + j) * DIMD);
#pragma unroll
        for (int i = 0; i < 4; i++) {
            int f4 = q + i * 8;
            float4 v = src[f4];
            int d = f4 * 4;
            xs[(d + 0) * 32 + j] = v.x; xs[(d + 1) * 32 + j] = v.y;
            xs[(d + 2) * 32 + j] = v.z; xs[(d + 3) * 32 + j] = v.w;
        }
    }
    __syncthreads();

    // Row sq-norms in fp64, rounded once to f32
    if (tid < 32) {
        double s0 = 0, s1 = 0, s2 = 0, s3 = 0;
#pragma unroll
        for (int d = 0; d < 128; d += 4) {
            double a = (double)xs[(d + 0) * 32 + tid]; s0 += a * a;
            double b = (double)xs[(d + 1) * 32 + tid]; s1 += b * b;
            double c = (double)xs[(d + 2) * 32 + tid]; s2 += c * c;
            double e = (double)xs[(d + 3) * 32 + tid]; s3 += e * e;
        }
        asq[tid] = (float)((s0 + s1) + (s2 + s3));
    }

    // Per-thread rows (local): 2w, 2w+1, 2w+16, 2w+17
    int rows[4] = { r0 + 2 * w, r0 + 2 * w + 1, r0 + 2 * w + 16, r0 + 2 * w + 17 };
    float bestv[4] = { -1e30f, -1e30f, -1e30f, -1e30f };
    int   besti[4] = { 0, 0, 0, 0 };

    for (int tt = 0; tt < NTILES; tt++) {
        const int cbase = tt * CT;
        __syncthreads();
        {   // load codebook tile transposed
            int c = tid >> 1, h = tid & 1;
            const float4* src = (const float4*)(cb + (size_t)(cbase + c) * DIMD + h * 64);
#pragma unroll
            for (int i = 0; i < 16; i++) {
                float4 v = src[i];
                int d = h * 64 + i * 4;
                cs[(d + 0) * 128 + c] = v.x; cs[(d + 1) * 128 + c] = v.y;
                cs[(d + 2) * 128 + c] = v.z; cs[(d + 3) * 128 + c] = v.w;
            }
            if (tid < 128) bsq[tid] = g_csq[cbase + tid];
        }
        __syncthreads();

        float acc[4][4];
#pragma unroll
        for (int r = 0; r < 4; r++)
#pragma unroll
            for (int c = 0; c < 4; c++) acc[r][c] = 0.0f;

#pragma unroll 8
        for (int k = 0; k < 128; k++) {
            float2 xa = *(const float2*)&xs[k * 32 + 2 * w];
            float2 xb = *(const float2*)&xs[k * 32 + 2 * w + 16];
            float4 cv = *(const float4*)&cs[k * 128 + 4 * l];
            acc[0][0] += xa.x * cv.x; acc[0][1] += xa.x * cv.y; acc[0][2] += xa.x * cv.z; acc[0][3] += xa.x * cv.w;
            acc[1][0] += xa.y * cv.x; acc[1][1] += xa.y * cv.y; acc[1][2] += xa.y * cv.z; acc[1][3] += xa.y * cv.w;
            acc[2][0] += xb.x * cv.x; acc[2][1] += xb.x * cv.y; acc[2][2] += xb.x * cv.z; acc[2][3] += xb.x * cv.w;
            acc[3][0] += xb.y * cv.x; acc[3][1] += xb.y * cv.y; acc[3][2] += xb.y * cv.z; acc[3][3] += xb.y * cv.w;
        }

        float aa[4] = { asq[2 * w], asq[2 * w + 1], asq[2 * w + 16], asq[2 * w + 17] };
#pragma unroll
        for (int cc = 0; cc < 4; cc++) {
            int code = cbase + 4 * l + cc;
            float b = bsq[4 * l + cc];
#pragma unroll
            for (int r = 0; r < 4; r++) {
                uint32_t ctr = (uint32_t)rows[r] * 1024u + (uint32_t)code;
                float g = gumbel_of(tf_xor(0u, ctr));
                // d2 = fl(fl(a+b) - fl(2*dot)) — exact reference op sequence
                float d2 = __fsub_rn(__fadd_rn(aa[r], b), __fmul_rn(2.0f, acc[r][cc]));
                float z = __fsub_rn(g, sqrtf(fmaxf(d2, 1e-12f)));
                if (z > bestv[r]) { bestv[r] = z; besti[r] = code; }
            }
        }
    }

    // Warp argmax reduce (ties -> lowest index), write one-hot + idx
#pragma unroll
    for (int r = 0; r < 4; r++) {
        float v = bestv[r];
        int   i = besti[r];
#pragma unroll
        for (int o = 16; o > 0; o >>= 1) {
            float v2 = __shfl_down_sync(0xffffffffu, v, o);
            int   i2 = __shfl_down_sync(0xffffffffu, i, o);
            if (v2 > v || (v2 == v && i2 < i)) { v = v2; i = i2; }
        }
        if (l == 0) {
            g_idx[rows[r]] = i;
            codes[(size_t)rows[r] * KC + i] = 1.0f;
        }
    }
}

// ---- scatter + loss (deterministic integer fixed-point atomics) ----
__global__ void __launch_bounds__(256) k_scatter(const float* __restrict__ x,
                                                 const float* __restrict__ cb) {
    int t = threadIdx.x;
    int d = t & 127, sub = t >> 7;
    int row = blockIdx.x * 2 + sub;
    int idx = g_idx[row];
    float xv = x[(size_t)row * DIMD + d];
    float cv = cb[(size_t)idx * DIMD + d];
    float diff = cv - xv;
    long long q = llrint((double)diff * (double)diff * 1073741824.0);   // 2^30
    __shared__ unsigned long long red[256];
    red[t] = (unsigned long long)q;
    __syncthreads();
    for (int o = 128; o > 0; o >>= 1) { if (t < o) red[t] += red[t + o]; __syncthreads(); }
    if (t == 0) atomicAdd(&g_loss, red[0]);
    long long sv = llrint((double)xv * 1099511627776.0);                // 2^40
    atomicAdd(&g_S[(size_t)idx * DIMD + d], (unsigned long long)sv);
}

// ---- finalize: loss scalar + EMA codebook ----
__global__ void k_final(const float* __restrict__ cb, float* __restrict__ out, size_t osz) {
    const size_t base = (size_t)NROWS * KC;
    if (osz < base + 1 + (size_t)KC * DIMD) return;
    int k = blockIdx.x, d = threadIdx.x;
    if (k < KC) {
        long long s = (long long)g_S[k * DIMD + d];
        float sum = (float)((double)s * (1.0 / 1099511627776.0));
        out[base + 1 + (size_t)k * DIMD + d] = 0.99f * cb[k * DIMD + d]
                                             + (float)(1.0 - 0.99) * sum;
    } else if (d == 0) {
        double sq = (double)(long long)g_loss * (1.0 / 1073741824.0);
        out[base] = (float)(1.25 * sq / 8388608.0);
    }
}

extern "C" void kernel_launch(void* const* d_in, const int* in_sizes, int n_in,
                              void* d_out, int out_size) {
    const float* x  = (const float*)d_in[0];
    const float* cb = (const float*)d_in[1];
    float* out = (float*)d_out;

    cudaFuncSetAttribute(k_main, cudaFuncAttributeMaxDynamicSharedMemorySize, SMEMSZ);

    size_t codes_elems = (size_t)NROWS * KC;
    size_t zn = (size_t)out_size < codes_elems ? (size_t)out_size : codes_elems;
    cudaMemsetAsync(out, 0, zn * sizeof(float));

    k_prep<<<KC, 128>>>(cb);
    k_main<<<NROWS / 32, 256, SMEMSZ>>>(x, cb, out);
    k_scatter<<<NROWS / 2, 256>>>(x, cb);
    k_final<<<KC + 1, 128>>>(cb, out, (size_t)out_size);
}

// round 6
// speedup vs baseline: 1.2911x; 1.2911x over previous
#include <cuda_runtime.h>
#include <cstdint>
#include <cstddef>

#define NROWS 65536
#define DIMD  128
#define KC    1024
#define CT    128
#define NTILES (KC / CT)
#define RPB   64     // rows per block
#define SMEMSZ (128*64*4 + 128*128*4 + 64*4 + 128*4)

// Device-global scratch (allocation-free per harness rules)
__device__ unsigned long long g_S[KC * DIMD];  // fixed-point scatter sums (x * 2^40)
__device__ unsigned long long g_loss;          // fixed-point sum of sq diffs (* 2^30)
__device__ float g_csq[KC];
__device__ int   g_idx[NROWS];

// threefry2x32, key = jax.random.key(42) = [0, 42]; partitionable 32-bit draws:
// counter (hi=0, lo=j), bits = out0 ^ out1.  (Verified passing in R5.)
__device__ __forceinline__ uint32_t tf_xor(uint32_t c0, uint32_t c1) {
    const uint32_t ks0 = 0u, ks1 = 42u, ks2 = 0x1BD11BF0u; // 0x1BD11BDA ^ 0 ^ 42
    uint32_t x0 = c0 + ks0, x1 = c1 + ks1;
#define TFR(r) { x0 += x1; x1 = __funnelshift_l(x1, x1, (r)); x1 ^= x0; }
    TFR(13) TFR(15) TFR(26) TFR(6)   x0 += ks1; x1 += ks2 + 1u;
    TFR(17) TFR(29) TFR(16) TFR(24)  x0 += ks2; x1 += ks0 + 2u;
    TFR(13) TFR(15) TFR(26) TFR(6)   x0 += ks0; x1 += ks1 + 3u;
    TFR(17) TFR(29) TFR(16) TFR(24)  x0 += ks1; x1 += ks2 + 4u;
    TFR(13) TFR(15) TFR(26) TFR(6)   x0 += ks2; x1 += ks0 + 5u;
#undef TFR
    return x0 ^ x1;
}

// JAX gumbel: u = max(tiny, fl(bits_float - 1) + tiny); g = -log(-log(u))
__device__ __forceinline__ float gumbel_of(uint32_t bits) {
    const float tiny = 1.17549435e-38f;
    float f = __fsub_rn(__uint_as_float((bits >> 9) | 0x3F800000u), 1.0f);
    float u = fmaxf(tiny, __fadd_rn(f, tiny));
    return -logf(-logf(u));
}

// Packed dual-FMA: d.lo += a.lo*b.lo, d.hi += a.hi*b.hi (each IEEE fp32 rn)
__device__ __forceinline__ void ffma2(unsigned long long& d,
                                      unsigned long long a,
                                      unsigned long long b) {
    asm("fma.rn.f32x2 %0, %1, %2, %0;" : "+l"(d) : "l"(a), "l"(b));
}
__device__ __forceinline__ unsigned long long dup2(float v) {
    unsigned long long r;
    asm("mov.b64 %0, {%1, %1};" : "=l"(r) : "f"(v));
    return r;
}

// ---- prep: zero accumulators, fp64-exact codebook sq-norms rounded to f32 ----
__global__ void k_prep(const float* __restrict__ cb) {
    int k = blockIdx.x, t = threadIdx.x;
    g_S[k * DIMD + t] = 0ull;
    if (k == 0 && t == 0) g_loss = 0ull;
    float v = cb[k * DIMD + t];
    __shared__ double red[128];
    red[t] = (double)v * (double)v;
    __syncthreads();
    for (int o = 64; o > 0; o >>= 1) { if (t < o) red[t] += red[t + o]; __syncthreads(); }
    if (t == 0) g_csq[k] = (float)red[0];
}

// ---- main: distances + gumbel + argmax + full one-hot row write ----
// 64 rows per block; warp w owns rows [8w, 8w+8); thread covers 8 rows x 4 codes.
__global__ void __launch_bounds__(256, 2) k_main(const float* __restrict__ x,
                                                 const float* __restrict__ cb,
                                                 float* __restrict__ codes) {
    extern __shared__ float sm[];
    float* xs  = sm;                  // [128][64]  x tile transposed [d][localrow]
    float* cs  = sm + 128 * 64;       // [128][128] codebook tile transposed [d][code]
    float* asq = cs + 128 * 128;      // [64]
    float* bsq = asq + 64;            // [128]

    const int tid = threadIdx.x;
    const int w = tid >> 5, l = tid & 31;
    const int r0 = blockIdx.x * RPB;

    // Load x tile transposed: row j = tid>>2 (0..63), quarter q = tid&3
    {
        int j = tid >> 2, q = tid & 3;
        const float4* src = (const float4*)(x + (size_t)(r0 + j) * DIMD);
#pragma unroll
        for (int i = 0; i < 8; i++) {
            int f4 = q * 8 + i;
            float4 v = src[f4];
            int d = f4 * 4;
            xs[(d + 0) * 64 + j] = v.x; xs[(d + 1) * 64 + j] = v.y;
            xs[(d + 2) * 64 + j] = v.z; xs[(d + 3) * 64 + j] = v.w;
        }
    }
    __syncthreads();

    // Row sq-norms in fp64, rounded once to f32
    if (tid < 64) {
        double s0 = 0, s1 = 0, s2 = 0, s3 = 0;
#pragma unroll
        for (int d = 0; d < 128; d += 4) {
            double a = (double)xs[(d + 0) * 64 + tid]; s0 += a * a;
            double b = (double)xs[(d + 1) * 64 + tid]; s1 += b * b;
            double c = (double)xs[(d + 2) * 64 + tid]; s2 += c * c;
            double e = (double)xs[(d + 3) * 64 + tid]; s3 += e * e;
        }
        asq[tid] = (float)((s0 + s1) + (s2 + s3));
    }

    float bestv[8];
    int   besti[8];
#pragma unroll
    for (int r = 0; r < 8; r++) { bestv[r] = -1e30f; besti[r] = 0; }

    for (int tt = 0; tt < NTILES; tt++) {
        const int cbase = tt * CT;
        __syncthreads();
        {   // load codebook tile transposed
            int c = tid >> 1, h = tid & 1;
            const float4* src = (const float4*)(cb + (size_t)(cbase + c) * DIMD + h * 64);
#pragma unroll
            for (int i = 0; i < 16; i++) {
                float4 v = src[i];
                int d = h * 64 + i * 4;
                cs[(d + 0) * 128 + c] = v.x; cs[(d + 1) * 128 + c] = v.y;
                cs[(d + 2) * 128 + c] = v.z; cs[(d + 3) * 128 + c] = v.w;
            }
            if (tid < 128) bsq[tid] = g_csq[cbase + tid];
        }
        __syncthreads();

        // accq[p][c]: packed accumulator for row pair (8w+2p, 8w+2p+1), code 4l+c
        unsigned long long accq[4][4];
#pragma unroll
        for (int p = 0; p < 4; p++)
#pragma unroll
            for (int c = 0; c < 4; c++) accq[p][c] = 0ull;

#pragma unroll 8
        for (int k = 0; k < 128; k++) {
            const unsigned long long* xp =
                (const unsigned long long*)(xs + k * 64 + 8 * w);
            unsigned long long a0 = xp[0], a1 = xp[1], a2 = xp[2], a3 = xp[3];
            float4 cv = *(const float4*)&cs[k * 128 + 4 * l];
            unsigned long long bx = dup2(cv.x), by = dup2(cv.y),
                               bz = dup2(cv.z), bw = dup2(cv.w);
            ffma2(accq[0][0], a0, bx); ffma2(accq[0][1], a0, by);
            ffma2(accq[0][2], a0, bz); ffma2(accq[0][3], a0, bw);
            ffma2(accq[1][0], a1, bx); ffma2(accq[1][1], a1, by);
            ffma2(accq[1][2], a1, bz); ffma2(accq[1][3], a1, bw);
            ffma2(accq[2][0], a2, bx); ffma2(accq[2][1], a2, by);
            ffma2(accq[2][2], a2, bz); ffma2(accq[2][3], a2, bw);
            ffma2(accq[3][0], a3, bx); ffma2(accq[3][1], a3, by);
            ffma2(accq[3][2], a3, bz); ffma2(accq[3][3], a3, bw);
        }

        float aa[8];
#pragma unroll
        for (int r = 0; r < 8; r++) aa[r] = asq[8 * w + r];

#pragma unroll
        for (int cc = 0; cc < 4; cc++) {
            int code = cbase + 4 * l + cc;
            float b = bsq[4 * l + cc];
#pragma unroll
            for (int p = 0; p < 4; p++) {
                float dlo = __uint_as_float((uint32_t)accq[p][cc]);
                float dhi = __uint_as_float((uint32_t)(accq[p][cc] >> 32));
                int rlo = r0 + 8 * w + 2 * p;
                uint32_t clo = (uint32_t)rlo * 1024u + (uint32_t)code;
                float glo = gumbel_of(tf_xor(0u, clo));
                float ghi = gumbel_of(tf_xor(0u, clo + 1024u));
                // d2 = fl(fl(a+b) - fl(2*dot)) — exact reference op sequence
                float d2l = __fsub_rn(__fadd_rn(aa[2 * p], b),     __fmul_rn(2.0f, dlo));
                float d2h = __fsub_rn(__fadd_rn(aa[2 * p + 1], b), __fmul_rn(2.0f, dhi));
                float zl = __fsub_rn(glo, sqrtf(fmaxf(d2l, 1e-12f)));
                float zh = __fsub_rn(ghi, sqrtf(fmaxf(d2h, 1e-12f)));
                if (zl > bestv[2 * p])     { bestv[2 * p] = zl;     besti[2 * p] = code; }
                if (zh > bestv[2 * p + 1]) { bestv[2 * p + 1] = zh; besti[2 * p + 1] = code; }
            }
        }
    }

    // Warp argmax reduce per row (ties -> lowest index), then write full one-hot rows
#pragma unroll
    for (int r = 0; r < 8; r++) {
        float v = bestv[r];
        int   i = besti[r];
#pragma unroll
        for (int o = 16; o > 0; o >>= 1) {
            float v2 = __shfl_down_sync(0xffffffffu, v, o);
            int   i2 = __shfl_down_sync(0xffffffffu, i, o);
            if (v2 > v || (v2 == v && i2 < i)) { v = v2; i = i2; }
        }
        int win = __shfl_sync(0xffffffffu, i, 0);   // broadcast winning code
        int grow = r0 + 8 * w + r;
        if (l == 0) g_idx[grow] = win;
        // each lane writes 32 floats (8 x float4), zeros + the single 1.0
        float4* dst = (float4*)(codes + (size_t)grow * KC + 32 * l);
        int rel = win - 32 * l;
#pragma unroll
        for (int q2 = 0; q2 < 8; q2++) {
            float4 v4 = make_float4(0.f, 0.f, 0.f, 0.f);
            int d = rel - 4 * q2;
            if (d == 0) v4.x = 1.0f; else if (d == 1) v4.y = 1.0f;
            else if (d == 2) v4.z = 1.0f; else if (d == 3) v4.w = 1.0f;
            dst[q2] = v4;
        }
    }
}

// ---- scatter + loss (deterministic integer fixed-point atomics) ----
__global__ void __launch_bounds__(256) k_scatter(const float* __restrict__ x,
                                                 const float* __restrict__ cb) {
    int t = threadIdx.x;
    int d = t & 127, sub = t >> 7;
    int row = blockIdx.x * 2 + sub;
    int idx = g_idx[row];
    float xv = x[(size_t)row * DIMD + d];
    float cv = cb[(size_t)idx * DIMD + d];
    float diff = cv - xv;
    long long q = llrint((double)diff * (double)diff * 1073741824.0);   // 2^30
    __shared__ unsigned long long red[256];
    red[t] = (unsigned long long)q;
    __syncthreads();
    for (int o = 128; o > 0; o >>= 1) { if (t < o) red[t] += red[t + o]; __syncthreads(); }
    if (t == 0) atomicAdd(&g_loss, red[0]);
    long long sv = llrint((double)xv * 1099511627776.0);                // 2^40
    atomicAdd(&g_S[(size_t)idx * DIMD + d], (unsigned long long)sv);
}

// ---- finalize: loss scalar + EMA codebook ----
__global__ void k_final(const float* __restrict__ cb, float* __restrict__ out, size_t osz) {
    const size_t base = (size_t)NROWS * KC;
    if (osz < base + 1 + (size_t)KC * DIMD) return;
    int k = blockIdx.x, d = threadIdx.x;
    if (k < KC) {
        long long s = (long long)g_S[k * DIMD + d];
        float sum = (float)((double)s * (1.0 / 1099511627776.0));
        out[base + 1 + (size_t)k * DIMD + d] = 0.99f * cb[k * DIMD + d]
                                             + (float)(1.0 - 0.99) * sum;
    } else if (d == 0) {
        double sq = (double)(long long)g_loss * (1.0 / 1073741824.0);
        out[base] = (float)(1.25 * sq / 8388608.0);
    }
}

extern "C" void kernel_launch(void* const* d_in, const int* in_sizes, int n_in,
                              void* d_out, int out_size) {
    const float* x  = (const float*)d_in[0];
    const float* cb = (const float*)d_in[1];
    float* out = (float*)d_out;

    cudaFuncSetAttribute(k_main, cudaFuncAttributeMaxDynamicSharedMemorySize, SMEMSZ);

    k_prep<<<KC, 128>>>(cb);
    k_main<<<NROWS / RPB, 256, SMEMSZ>>>(x, cb, out);
    k_scatter<<<NROWS / 2, 256>>>(x, cb);
    k_final<<<KC + 1, 128>>>(cb, out, (size_t)out_size);
}